// round 3
// baseline (speedup 1.0000x reference)
#include <cuda_runtime.h>
#include <cstdint>
#include <cstddef>

// ---------------------------------------------------------------------------
// Constants: decomposition filters (from reference)
// ---------------------------------------------------------------------------
__constant__ float c_lo[8] = {
    -0.010597401784997278f,  0.032883011666982945f,  0.030841381835986965f,
    -0.18703481171888114f,  -0.02798376941698385f,   0.6308807679295904f,
     0.7148465705525415f,    0.23037781330885523f};
__constant__ float c_hi[8] = {
    -0.23037781330885523f,   0.7148465705525415f,   -0.6308807679295904f,
    -0.02798376941698385f,   0.18703481171888114f,   0.030841381835986965f,
    -0.032883011666982945f, -0.010597401784997278f};

// Effective projection: Weff[k][o], k = c*8 + j (24), o (128). Row-major, o contiguous.
__device__ float g_weff[24 * 128];

// ---------------------------------------------------------------------------
// Exact single-level pywt dwt, mode='symmetric'
// ---------------------------------------------------------------------------
__device__ __forceinline__ void dwt_dev(const float* a, int n, float* lo, float* hi) {
    int m = (n + 7) / 2;
    for (int i = 0; i < m; ++i) {
        float accL = 0.f, accH = 0.f;
        for (int f = 0; f < 8; ++f) {
            int t = (1 + 2 * i + f) - 7;
            if (t < 0) t = -1 - t;
            else if (t >= n) t = 2 * n - 1 - t;
            float xv = a[t];
            accL += xv * c_lo[7 - f];
            accH += xv * c_hi[7 - f];
        }
        lo[i] = accL;
        hi[i] = accH;
    }
}

// ---------------------------------------------------------------------------
// Init kernel: build M (28x8) via basis vectors, fold into Weff.
// ---------------------------------------------------------------------------
__global__ void init_weff_kernel(const float* __restrict__ W) {
    __shared__ float sM[28][8];
    int t = threadIdx.x;
    if (t < 8) {
        float win[8];
        #pragma unroll
        for (int i = 0; i < 8; ++i) win[i] = (i == t) ? 1.f : 0.f;
        float cA[7], cD[7], aa[7], ad[7], da[7], dd[7];
        dwt_dev(win, 8, cA, cD);
        dwt_dev(cA, 7, aa, ad);
        dwt_dev(cD, 7, da, dd);
        for (int i = 0; i < 7; ++i) {
            sM[i][t]      = aa[i];
            sM[7 + i][t]  = ad[i];
            sM[14 + i][t] = dd[i];
            sM[21 + i][t] = da[i];
        }
    }
    __syncthreads();
    int o = threadIdx.x;  // 0..127
    for (int c = 0; c < 3; ++c) {
        for (int j = 0; j < 8; ++j) {
            float s = 0.f;
            #pragma unroll
            for (int k = 0; k < 28; ++k) s += sM[k][j] * W[o * 84 + c * 28 + k];
            g_weff[(c * 8 + j) * 128 + o] = s;
        }
    }
}

// ---------------------------------------------------------------------------
// Packed f32x2 helpers
// ---------------------------------------------------------------------------
__device__ __forceinline__ uint64_t ffma2(uint64_t a, uint64_t b, uint64_t c) {
    uint64_t d;
    asm("fma.rn.f32x2 %0, %1, %2, %3;" : "=l"(d) : "l"(a), "l"(b), "l"(c));
    return d;
}
__device__ __forceinline__ uint64_t bcast2(float x) {
    uint64_t d;
    unsigned xi = __float_as_uint(x);
    asm("mov.b64 %0, {%1, %1};" : "=l"(d) : "r"(xi));
    return d;
}
__device__ __forceinline__ float2 unpack2(uint64_t u) {
    float2 f;
    asm("mov.b64 {%0, %1}, %2;" : "=f"(f.x), "=f"(f.y) : "l"(u));
    return f;
}
__device__ __forceinline__ float f4_get(const float4& v, int i) {
    switch (i) {
        case 0: return v.x;
        case 1: return v.y;
        case 2: return v.z;
        default: return v.w;
    }
}

// ---------------------------------------------------------------------------
// Main kernel:
//   grid = (P/64 = 16, V = 25, B = 32), block = 256 (16x16)
//   Block computes 64 p-rows x 128 o-cols for one (b, v).
//   Thread (tx, ty): rows p_local = ty + 16*r (r 0..3), cols o = tx*8 .. tx*8+7
// ---------------------------------------------------------------------------
static constexpr int XSTRIDE = 264;  // 260 used, padded; 264*4 bytes = 16B-aligned stride

__global__ void __launch_bounds__(256, 3)
wavelet_embed_kernel(const float* __restrict__ x, float* __restrict__ out) {
    __shared__ float s_w[24 * 128];        // Weff, k-major, o contiguous (12 KB)
    __shared__ float s_x[3 * XSTRIDE];     // 3 channels x 260 t samples

    const int tid  = threadIdx.x;
    const int tile = blockIdx.x;   // 0..15
    const int v    = blockIdx.y;   // 0..24
    const int b    = blockIdx.z;   // 0..31
    const int p0   = tile * 64;
    const int t0   = 4 * p0;

    // stage Weff with float4 (coalesced, 3 iters/thread)
    {
        const float4* src = reinterpret_cast<const float4*>(g_weff);
        float4* dst = reinterpret_cast<float4*>(s_w);
        #pragma unroll
        for (int i = tid; i < 24 * 32; i += 256) dst[i] = src[i];
    }

    // stage x: t in [t0, t0+259], 3 channels, fixed v. Edge-clamp at 4095.
    const float* xb = x + ((size_t)b * 3) * 4096 * 25 + v;
    #pragma unroll
    for (int i = tid; i < 3 * 260; i += 256) {
        int c  = i / 260;
        int tt = i - c * 260;
        int t  = t0 + tt;
        if (t > 4095) t = 4095;
        s_x[c * XSTRIDE + tt] = xb[((size_t)c * 4096 + t) * 25];
    }
    __syncthreads();

    const int tx = tid & 15;
    const int ty = tid >> 4;

    uint64_t acc[4][4];
    #pragma unroll
    for (int r = 0; r < 4; ++r)
        #pragma unroll
        for (int q = 0; q < 4; ++q) acc[r][q] = 0ull;

    // Weff as 16B vectors: pair q of thread tx at uint64 index k*64 + tx*4 + 2q
    const ulonglong2* wq = reinterpret_cast<const ulonglong2*>(s_w);

    #pragma unroll
    for (int c = 0; c < 3; ++c) {
        // preload the 8 window samples for each of this thread's 4 rows (LDS.128)
        float4 xv[4][2];
        const float4* xp = reinterpret_cast<const float4*>(s_x + c * XSTRIDE) + ty;
        #pragma unroll
        for (int r = 0; r < 4; ++r) {
            xv[r][0] = xp[16 * r];
            xv[r][1] = xp[16 * r + 1];
        }
        #pragma unroll
        for (int j = 0; j < 8; ++j) {
            const int k = c * 8 + j;
            const ulonglong2 wA = wq[k * 32 + tx * 2];
            const ulonglong2 wB = wq[k * 32 + tx * 2 + 1];
            #pragma unroll
            for (int r = 0; r < 4; ++r) {
                const float xs = (j < 4) ? f4_get(xv[r][0], j) : f4_get(xv[r][1], j - 4);
                const uint64_t xx = bcast2(xs);
                acc[r][0] = ffma2(xx, wA.x, acc[r][0]);
                acc[r][1] = ffma2(xx, wA.y, acc[r][1]);
                acc[r][2] = ffma2(xx, wB.x, acc[r][2]);
                acc[r][3] = ffma2(xx, wB.y, acc[r][3]);
            }
        }
    }

    // store: out[(b*25600 + v*1024 + p) * 128 + o]
    const size_t rowbase = (size_t)b * 25600 + (size_t)v * 1024 + p0;
    #pragma unroll
    for (int r = 0; r < 4; ++r) {
        const int p_local = ty + 16 * r;
        float* op = out + (rowbase + p_local) * 128 + tx * 8;
        float2 a0 = unpack2(acc[r][0]);
        float2 a1 = unpack2(acc[r][1]);
        float2 a2 = unpack2(acc[r][2]);
        float2 a3 = unpack2(acc[r][3]);
        reinterpret_cast<float4*>(op)[0] = make_float4(a0.x, a0.y, a1.x, a1.y);
        reinterpret_cast<float4*>(op)[1] = make_float4(a2.x, a2.y, a3.x, a3.y);
    }
}

// ---------------------------------------------------------------------------
// Launch
// ---------------------------------------------------------------------------
extern "C" void kernel_launch(void* const* d_in, const int* in_sizes, int n_in,
                              void* d_out, int out_size) {
    const float* x = (const float*)d_in[0];  // (32, 3, 4096, 25) fp32
    const float* W = (const float*)d_in[1];  // (128, 84) fp32
    float* out = (float*)d_out;              // (32, 25600, 128) fp32

    init_weff_kernel<<<1, 128>>>(W);
    dim3 grid(16, 25, 32);
    wavelet_embed_kernel<<<grid, 256>>>(x, out);
}

// round 4
// speedup vs baseline: 1.4043x; 1.4043x over previous
#include <cuda_runtime.h>
#include <cstdint>
#include <cstddef>

// ---------------------------------------------------------------------------
// Constants: decomposition filters (from reference)
// ---------------------------------------------------------------------------
__constant__ float c_lo[8] = {
    -0.010597401784997278f,  0.032883011666982945f,  0.030841381835986965f,
    -0.18703481171888114f,  -0.02798376941698385f,   0.6308807679295904f,
     0.7148465705525415f,    0.23037781330885523f};
__constant__ float c_hi[8] = {
    -0.23037781330885523f,   0.7148465705525415f,   -0.6308807679295904f,
    -0.02798376941698385f,   0.18703481171888114f,   0.030841381835986965f,
    -0.032883011666982945f, -0.010597401784997278f};

// Effective projection: Weff[k][o], k = c*8 + j (24), o (128). Row-major, o contiguous.
__device__ float g_weff[24 * 128];

// ---------------------------------------------------------------------------
// Exact single-level pywt dwt, mode='symmetric'
// ---------------------------------------------------------------------------
__device__ __forceinline__ void dwt_dev(const float* a, int n, float* lo, float* hi) {
    int m = (n + 7) / 2;
    for (int i = 0; i < m; ++i) {
        float accL = 0.f, accH = 0.f;
        for (int f = 0; f < 8; ++f) {
            int t = (1 + 2 * i + f) - 7;
            if (t < 0) t = -1 - t;
            else if (t >= n) t = 2 * n - 1 - t;
            float xv = a[t];
            accL += xv * c_lo[7 - f];
            accH += xv * c_hi[7 - f];
        }
        lo[i] = accL;
        hi[i] = accH;
    }
}

// ---------------------------------------------------------------------------
// Init kernel: build M (28x8) via basis vectors, fold into Weff.
// ---------------------------------------------------------------------------
__global__ void init_weff_kernel(const float* __restrict__ W) {
    __shared__ float sM[28][8];
    int t = threadIdx.x;
    if (t < 8) {
        float win[8];
        #pragma unroll
        for (int i = 0; i < 8; ++i) win[i] = (i == t) ? 1.f : 0.f;
        float cA[7], cD[7], aa[7], ad[7], da[7], dd[7];
        dwt_dev(win, 8, cA, cD);
        dwt_dev(cA, 7, aa, ad);
        dwt_dev(cD, 7, da, dd);
        for (int i = 0; i < 7; ++i) {
            sM[i][t]      = aa[i];
            sM[7 + i][t]  = ad[i];
            sM[14 + i][t] = dd[i];
            sM[21 + i][t] = da[i];
        }
    }
    __syncthreads();
    int o = threadIdx.x;  // 0..127
    for (int c = 0; c < 3; ++c) {
        for (int j = 0; j < 8; ++j) {
            float s = 0.f;
            #pragma unroll
            for (int k = 0; k < 28; ++k) s += sM[k][j] * W[o * 84 + c * 28 + k];
            g_weff[(c * 8 + j) * 128 + o] = s;
        }
    }
}

// ---------------------------------------------------------------------------
// Packed f32x2 helpers
// ---------------------------------------------------------------------------
__device__ __forceinline__ uint64_t ffma2(uint64_t a, uint64_t b, uint64_t c) {
    uint64_t d;
    asm("fma.rn.f32x2 %0, %1, %2, %3;" : "=l"(d) : "l"(a), "l"(b), "l"(c));
    return d;
}
__device__ __forceinline__ uint64_t bcast2(float x) {
    uint64_t d;
    unsigned xi = __float_as_uint(x);
    asm("mov.b64 %0, {%1, %1};" : "=l"(d) : "r"(xi));
    return d;
}
__device__ __forceinline__ float2 unpack2(uint64_t u) {
    float2 f;
    asm("mov.b64 {%0, %1}, %2;" : "=f"(f.x), "=f"(f.y) : "l"(u));
    return f;
}
__device__ __forceinline__ float f4_get(const float4& v, int i) {
    switch (i) {
        case 0: return v.x;
        case 1: return v.y;
        case 2: return v.z;
        default: return v.w;
    }
}

// ---------------------------------------------------------------------------
// Main kernel (Weff in registers, warp-uniform x broadcast):
//   grid = (2, 25, 32), block = 256 (8 warps)
//   Block handles 512 consecutive p-rows x 128 o-cols of one (b, v).
//   Lane l owns o-cols 4l..4l+3 (each warp covers all 128 cols).
//   Warp w streams rows [w*64, w*64+64), 4 rows per group.
// ---------------------------------------------------------------------------
static constexpr int ROWS_PB = 512;
static constexpr int XLEN = 4 * ROWS_PB + 4;   // 2052 samples per channel

__global__ void __launch_bounds__(256, 1)
wavelet_embed_kernel(const float* __restrict__ x, float* __restrict__ out) {
    __shared__ float s_x[3 * XLEN];    // 24.6 KB

    const int tid  = threadIdx.x;
    const int half = blockIdx.x;   // 0..1
    const int v    = blockIdx.y;   // 0..24
    const int b    = blockIdx.z;   // 0..31
    const int p0   = half * ROWS_PB;
    const int t0   = 4 * p0;

    // ---- stage x: t in [t0, t0+2051], 3 channels, fixed v, edge-clamp ----
    const float* xb = x + ((size_t)b * 3) * 4096 * 25 + v;
    for (int i = tid; i < 3 * XLEN; i += 256) {
        int c  = i / XLEN;
        int tt = i - c * XLEN;
        int t  = t0 + tt;
        if (t > 4095) t = 4095;
        s_x[i] = xb[((size_t)c * 4096 + t) * 25];
    }

    // ---- load this lane's Weff column slice into registers (one-time) ----
    const int lane = tid & 31;
    const int wid  = tid >> 5;
    ulonglong2 w[24];
    #pragma unroll
    for (int k = 0; k < 24; ++k)
        w[k] = *reinterpret_cast<const ulonglong2*>(g_weff + k * 128 + 4 * lane);

    __syncthreads();

    const size_t rowg = (size_t)b * 25600 + (size_t)v * 1024 + p0;
    const int rbase = wid * 64;

    for (int g = 0; g < 16; ++g) {
        const int r0 = rbase + g * 4;

        uint64_t acc[4][2];
        #pragma unroll
        for (int rr = 0; rr < 4; ++rr) { acc[rr][0] = 0ull; acc[rr][1] = 0ull; }

        #pragma unroll
        for (int c = 0; c < 3; ++c) {
            // warp-uniform vector loads: 8 window samples per row
            float4 xa[4], xb4[4];
            const float4* xp = reinterpret_cast<const float4*>(s_x + c * XLEN);
            #pragma unroll
            for (int rr = 0; rr < 4; ++rr) {
                xa[rr]  = xp[r0 + rr];       // samples j=0..3 of row r0+rr
                xb4[rr] = xp[r0 + rr + 1];   // samples j=4..7
            }
            #pragma unroll
            for (int j = 0; j < 8; ++j) {
                const int k = c * 8 + j;
                #pragma unroll
                for (int rr = 0; rr < 4; ++rr) {
                    const float xs = (j < 4) ? f4_get(xa[rr], j) : f4_get(xb4[rr], j - 4);
                    const uint64_t xx = bcast2(xs);
                    acc[rr][0] = ffma2(xx, w[k].x, acc[rr][0]);
                    acc[rr][1] = ffma2(xx, w[k].y, acc[rr][1]);
                }
            }
        }

        #pragma unroll
        for (int rr = 0; rr < 4; ++rr) {
            float2 a0 = unpack2(acc[rr][0]);
            float2 a1 = unpack2(acc[rr][1]);
            *reinterpret_cast<float4*>(out + (rowg + r0 + rr) * 128 + 4 * lane) =
                make_float4(a0.x, a0.y, a1.x, a1.y);
        }
    }
}

// ---------------------------------------------------------------------------
// Launch
// ---------------------------------------------------------------------------
extern "C" void kernel_launch(void* const* d_in, const int* in_sizes, int n_in,
                              void* d_out, int out_size) {
    const float* x = (const float*)d_in[0];  // (32, 3, 4096, 25) fp32
    const float* W = (const float*)d_in[1];  // (128, 84) fp32
    float* out = (float*)d_out;              // (32, 25600, 128) fp32

    init_weff_kernel<<<1, 128>>>(W);
    dim3 grid(2, 25, 32);
    wavelet_embed_kernel<<<grid, 256>>>(x, out);
}

// round 5
// speedup vs baseline: 1.6693x; 1.1887x over previous
#include <cuda_runtime.h>
#include <cstdint>
#include <cstddef>

// ---------------------------------------------------------------------------
// Constants: decomposition filters (from reference)
// ---------------------------------------------------------------------------
__constant__ float c_lo[8] = {
    -0.010597401784997278f,  0.032883011666982945f,  0.030841381835986965f,
    -0.18703481171888114f,  -0.02798376941698385f,   0.6308807679295904f,
     0.7148465705525415f,    0.23037781330885523f};
__constant__ float c_hi[8] = {
    -0.23037781330885523f,   0.7148465705525415f,   -0.6308807679295904f,
    -0.02798376941698385f,   0.18703481171888114f,   0.030841381835986965f,
    -0.032883011666982945f, -0.010597401784997278f};

// Effective projection: Weff[k][o], k = c*8 + j (24), o (128). Row-major, o contiguous.
__device__ float g_weff[24 * 128];

// ---------------------------------------------------------------------------
// Exact single-level pywt dwt, mode='symmetric'
// ---------------------------------------------------------------------------
__device__ __forceinline__ void dwt_dev(const float* a, int n, float* lo, float* hi) {
    int m = (n + 7) / 2;
    for (int i = 0; i < m; ++i) {
        float accL = 0.f, accH = 0.f;
        for (int f = 0; f < 8; ++f) {
            int t = (1 + 2 * i + f) - 7;
            if (t < 0) t = -1 - t;
            else if (t >= n) t = 2 * n - 1 - t;
            float xv = a[t];
            accL += xv * c_lo[7 - f];
            accH += xv * c_hi[7 - f];
        }
        lo[i] = accL;
        hi[i] = accH;
    }
}

// ---------------------------------------------------------------------------
// Init kernel: build M (28x8) via basis vectors, fold into Weff.
// ---------------------------------------------------------------------------
__global__ void init_weff_kernel(const float* __restrict__ W) {
    __shared__ float sM[28][8];
    int t = threadIdx.x;
    if (t < 8) {
        float win[8];
        #pragma unroll
        for (int i = 0; i < 8; ++i) win[i] = (i == t) ? 1.f : 0.f;
        float cA[7], cD[7], aa[7], ad[7], da[7], dd[7];
        dwt_dev(win, 8, cA, cD);
        dwt_dev(cA, 7, aa, ad);
        dwt_dev(cD, 7, da, dd);
        for (int i = 0; i < 7; ++i) {
            sM[i][t]      = aa[i];
            sM[7 + i][t]  = ad[i];
            sM[14 + i][t] = dd[i];
            sM[21 + i][t] = da[i];
        }
    }
    __syncthreads();
    int o = threadIdx.x;  // 0..127
    for (int c = 0; c < 3; ++c) {
        for (int j = 0; j < 8; ++j) {
            float s = 0.f;
            #pragma unroll
            for (int k = 0; k < 28; ++k) s += sM[k][j] * W[o * 84 + c * 28 + k];
            g_weff[(c * 8 + j) * 128 + o] = s;
        }
    }
}

// ---------------------------------------------------------------------------
// Packed f32x2 helpers
// ---------------------------------------------------------------------------
__device__ __forceinline__ uint64_t ffma2(uint64_t a, uint64_t b, uint64_t c) {
    uint64_t d;
    asm("fma.rn.f32x2 %0, %1, %2, %3;" : "=l"(d) : "l"(a), "l"(b), "l"(c));
    return d;
}
__device__ __forceinline__ uint64_t bcast2(float x) {
    uint64_t d;
    unsigned xi = __float_as_uint(x);
    asm("mov.b64 %0, {%1, %1};" : "=l"(d) : "r"(xi));
    return d;
}
__device__ __forceinline__ float2 unpack2(uint64_t u) {
    float2 f;
    asm("mov.b64 {%0, %1}, %2;" : "=f"(f.x), "=f"(f.y) : "l"(u));
    return f;
}
__device__ __forceinline__ float f4_get(const float4& v, int i) {
    switch (i) {
        case 0: return v.x;
        case 1: return v.y;
        case 2: return v.z;
        default: return v.w;
    }
}

// ---------------------------------------------------------------------------
// Main kernel (Weff in registers, warp-uniform x broadcast):
//   grid = (2, 25, 32), block = 256 (8 warps), 2 CTAs/SM target
//   Block handles 512 consecutive p-rows x 128 o-cols of one (b, v).
//   Lane l owns o-cols 4l..4l+3. Warp w streams rows [w*64, w*64+64),
//   4 rows per group, 5 overlapping float4 x-loads per (c, group).
// ---------------------------------------------------------------------------
static constexpr int ROWS_PB = 512;
static constexpr int XLEN = 4 * ROWS_PB + 4;   // 2052 samples per channel

__global__ void __launch_bounds__(256, 2)
wavelet_embed_kernel(const float* __restrict__ x, float* __restrict__ out) {
    __shared__ float s_x[3 * XLEN];    // 24.6 KB

    const int tid  = threadIdx.x;
    const int half = blockIdx.x;   // 0..1
    const int v    = blockIdx.y;   // 0..24
    const int b    = blockIdx.z;   // 0..31
    const int p0   = half * ROWS_PB;
    const int t0   = 4 * p0;

    // ---- stage x: t in [t0, t0+2051], 3 channels, fixed v, edge-clamp ----
    const float* xb = x + ((size_t)b * 3) * 4096 * 25 + v;
    for (int i = tid; i < 3 * XLEN; i += 256) {
        int c  = i / XLEN;
        int tt = i - c * XLEN;
        int t  = t0 + tt;
        if (t > 4095) t = 4095;
        s_x[i] = xb[((size_t)c * 4096 + t) * 25];
    }

    // ---- load this lane's Weff column slice into registers (one-time) ----
    const int lane = tid & 31;
    const int wid  = tid >> 5;
    ulonglong2 w[24];
    #pragma unroll
    for (int k = 0; k < 24; ++k)
        w[k] = *reinterpret_cast<const ulonglong2*>(g_weff + k * 128 + 4 * lane);

    __syncthreads();

    const size_t rowg = (size_t)b * 25600 + (size_t)v * 1024 + p0;
    const int rbase = wid * 64;

    for (int g = 0; g < 16; ++g) {
        const int r0 = rbase + g * 4;

        uint64_t acc[4][2];
        #pragma unroll
        for (int rr = 0; rr < 4; ++rr) { acc[rr][0] = 0ull; acc[rr][1] = 0ull; }

        #pragma unroll
        for (int c = 0; c < 3; ++c) {
            // 5 overlapping warp-uniform float4 loads cover 4 rows' windows:
            // row rr uses xv[rr] (j=0..3) and xv[rr+1] (j=4..7)
            const float4* xp = reinterpret_cast<const float4*>(s_x + c * XLEN);
            float4 xv[5];
            #pragma unroll
            for (int i = 0; i < 5; ++i) xv[i] = xp[r0 + i];

            #pragma unroll
            for (int j = 0; j < 8; ++j) {
                const int k = c * 8 + j;
                #pragma unroll
                for (int rr = 0; rr < 4; ++rr) {
                    const float xs = (j < 4) ? f4_get(xv[rr], j) : f4_get(xv[rr + 1], j - 4);
                    const uint64_t xx = bcast2(xs);
                    acc[rr][0] = ffma2(xx, w[k].x, acc[rr][0]);
                    acc[rr][1] = ffma2(xx, w[k].y, acc[rr][1]);
                }
            }
        }

        #pragma unroll
        for (int rr = 0; rr < 4; ++rr) {
            float2 a0 = unpack2(acc[rr][0]);
            float2 a1 = unpack2(acc[rr][1]);
            *reinterpret_cast<float4*>(out + (rowg + r0 + rr) * 128 + 4 * lane) =
                make_float4(a0.x, a0.y, a1.x, a1.y);
        }
    }
}

// ---------------------------------------------------------------------------
// Launch
// ---------------------------------------------------------------------------
extern "C" void kernel_launch(void* const* d_in, const int* in_sizes, int n_in,
                              void* d_out, int out_size) {
    const float* x = (const float*)d_in[0];  // (32, 3, 4096, 25) fp32
    const float* W = (const float*)d_in[1];  // (128, 84) fp32
    float* out = (float*)d_out;              // (32, 25600, 128) fp32

    init_weff_kernel<<<1, 128>>>(W);
    dim3 grid(2, 25, 32);
    wavelet_embed_kernel<<<grid, 256>>>(x, out);
}